// round 15
// baseline (speedup 1.0000x reference)
#include <cuda_runtime.h>
#include <cuda_fp16.h>

typedef unsigned int u32;

#define TPTS 10
#define CTA 512

// ---- smem byte offsets ----
#define EXPW   19200
#define SW1F   0
#define SW2F   6144
#define SW3F   14336
#define SB1    18432
#define SB2    18688
#define SB3    18944
#define SGW1F  153600     // 8192
#define SGW2F  161792     // 1024
#define SGB1   162816     // 256
#define SGB2   163072     // 32
#define SFBASE 163104     // F[wlow][e][lane][32B] = 65536
#define SMEM_BYTES 228640

// weights pre-arranged in B-fragment register order
__device__ __align__(16) u32 g_W1F[8*3*8*64];
__device__ __align__(16) u32 g_W2F[8*4*8*64];
__device__ __align__(16) u32 g_W3F[8*4*4*64];
__device__ __align__(16) u32 g_GW1F[4*8*64];
__device__ __align__(16) u32 g_GW2F[4*64];

static __device__ __forceinline__ u32 f2h2(float lo, float hi){
    u32 r; asm("cvt.rn.f16x2.f32 %0, %2, %1;" : "=r"(r) : "f"(lo), "f"(hi)); return r;
}
static __device__ __forceinline__ float2 h22f2(u32 h){
    __half2 v = *(__half2*)&h; return __half22float2(v);
}
static __device__ __forceinline__ u32 tanh_h2(u32 h){
    u32 r; asm("tanh.approx.f16x2 %0,%1;" : "=r"(r) : "r"(h)); return r;
}
static __device__ __forceinline__ float exp_fast(float x){
    float e; asm("ex2.approx.f32 %0,%1;" : "=f"(e) : "f"(x * 1.4426950408889634f)); return e;
}
static __device__ __forceinline__ float rcp_fast(float x){
    float r; asm("rcp.approx.f32 %0,%1;" : "=f"(r) : "f"(x)); return r;
}

#define MMA4(d, a0,a1,a2,a3, b) \
    asm volatile("mma.sync.aligned.m16n8k16.row.col.f32.f16.f16.f32 " \
        "{%0,%1,%2,%3},{%4,%5,%6,%7},{%8,%9},{%0,%1,%2,%3};" \
        : "+f"((d)[0]),"+f"((d)[1]),"+f"((d)[2]),"+f"((d)[3]) \
        : "r"(a0),"r"(a1),"r"(a2),"r"(a3),"r"((b).x),"r"((b).y))

#define MMA4_INIT(d, a0,a1,a2,a3, b) \
    asm volatile("mma.sync.aligned.m16n8k16.row.col.f32.f16.f16.f32 " \
        "{%0,%1,%2,%3},{%4,%5,%6,%7},{%8,%9},{%10,%10,%10,%10};" \
        : "=f"((d)[0]),"=f"((d)[1]),"=f"((d)[2]),"=f"((d)[3]) \
        : "r"(a0),"r"(a1),"r"(a2),"r"(a3),"r"((b).x),"r"((b).y),"f"(0.f))

static __device__ __forceinline__ void stage16(u32 dst, const char* src, int n16, int tid){
    for (int i = tid; i < n16; i += CTA)
        asm volatile("cp.async.cg.shared.global [%0],[%1],16;"
                     :: "r"(dst + (u32)i*16), "l"(src + i*16));
}

// epilogue for N=64 layers: bias add (fp32) -> fp16 pack -> tanh.f16x2 -> A-frags
#define EPI64(acc, biasptr, HA) { \
    const float* _b = (const float*)(biasptr); \
    _Pragma("unroll") \
    for (int j = 0; j < 8; j++){ \
        float2 bv = *(const float2*)(_b + j*8 + 2*q); \
        u32 p0 = f2h2((acc)[j*4+0] + bv.x, (acc)[j*4+1] + bv.y); \
        u32 p1 = f2h2((acc)[j*4+2] + bv.x, (acc)[j*4+3] + bv.y); \
        (HA)[(j>>1)*4 + (j&1)*2 + 0] = tanh_h2(p0); \
        (HA)[(j>>1)*4 + (j&1)*2 + 1] = tanh_h2(p1); \
    } }

// ---------------- weight frag-order pre-kernel ----------------
__global__ void conv_weights(const float* __restrict__ W1, const float* __restrict__ W2,
                             const float* __restrict__ W3, const float* __restrict__ Gw1,
                             const float* __restrict__ Gw2){
    int i0 = blockIdx.x*blockDim.x + threadIdx.x, st = gridDim.x*blockDim.x;
    for (int i = i0; i < 8*3*8*64; i += st){
        int r = i & 1, t = i >> 1, l = t & 31; t >>= 5;
        int j = t & 7; t >>= 3; int ks = t % 3, e = t / 3;
        int k = ks*16 + (l&3)*2 + r*8, n = j*8 + (l>>2);
        float lo = (k   < 33) ? W1[e*2112 + k*64 + n]     : 0.f;
        float hi = (k+1 < 33) ? W1[e*2112 + (k+1)*64 + n] : 0.f;
        __half2 h = __floats2half2_rn(lo, hi);
        g_W1F[i] = *(u32*)&h;
    }
    for (int i = i0; i < 8*4*8*64; i += st){
        int r = i & 1, t = i >> 1, l = t & 31; t >>= 5;
        int j = t & 7; t >>= 3; int ks = t & 3, e = t >> 2;
        int k = ks*16 + (l&3)*2 + r*8, n = j*8 + (l>>2);
        __half2 h = __floats2half2_rn(W2[e*4096 + k*64 + n], W2[e*4096 + (k+1)*64 + n]);
        g_W2F[i] = *(u32*)&h;
    }
    for (int i = i0; i < 8*4*4*64; i += st){
        int r = i & 1, t = i >> 1, l = t & 31; t >>= 5;
        int j = t & 3; t >>= 2; int ks = t & 3, e = t >> 2;
        int k = ks*16 + (l&3)*2 + r*8, n = j*8 + (l>>2);
        __half2 h = __floats2half2_rn(W3[e*2048 + k*32 + n], W3[e*2048 + (k+1)*32 + n]);
        g_W3F[i] = *(u32*)&h;
    }
    for (int i = i0; i < 4*8*64; i += st){
        int r = i & 1, t = i >> 1, l = t & 31; t >>= 5;
        int j = t & 7, ks = t >> 3;
        int k = ks*16 + (l&3)*2 + r*8, n = j*8 + (l>>2);
        __half2 h = __floats2half2_rn(Gw1[k*64 + n], Gw1[(k+1)*64 + n]);
        g_GW1F[i] = *(u32*)&h;
    }
    for (int i = i0; i < 4*64; i += st){
        int r = i & 1, t = i >> 1, l = t & 31; t >>= 5;
        int ks = t;
        int k = ks*16 + (l&3)*2 + r*8, n = l >> 2;
        __half2 h = __floats2half2_rn(Gw2[k*8 + n], Gw2[(k+1)*8 + n]);
        g_GW2F[i] = *(u32*)&h;
    }
}

// ---------------- main kernel ----------------
// 16 warps: warp pair (w, w+8) shares 16 rows; w does experts 0-3, w+8 experts 4-7.
__global__ void __launch_bounds__(CTA, 1)
ameode_mma(const float* __restrict__ x0, const float* __restrict__ tspan,
           const float* __restrict__ b1, const float* __restrict__ b2, const float* __restrict__ b3,
           const float* __restrict__ Gb1, const float* __restrict__ Gb2,
           float* __restrict__ out)
{
    extern __shared__ char smem[];
    u32 sb = (u32)__cvta_generic_to_shared(smem);
    const int tid = threadIdx.x, lane = tid & 31, warp = tid >> 5;
    const int half = warp >> 3, wlow = warp & 7;
    const int g = lane >> 2, q = lane & 3;
    const int row0 = blockIdx.x*128 + wlow*16 + g;    // rows row0, row0+8
    const int e0 = half * 4;

    // stage ALL 8 expert buffers + gating weights ONCE (read-only thereafter)
    #pragma unroll 1
    for (int e = 0; e < 8; e++){
        u32 bo = sb + (u32)e * EXPW;
        stage16(bo + SW1F, (const char*)g_W1F + e*6144, 384, tid);
        stage16(bo + SW2F, (const char*)g_W2F + e*8192, 512, tid);
        stage16(bo + SW3F, (const char*)g_W3F + e*4096, 256, tid);
        stage16(bo + SB1, (const char*)(b1 + e*64), 16, tid);
        stage16(bo + SB2, (const char*)(b2 + e*64), 16, tid);
        stage16(bo + SB3, (const char*)(b3 + e*32),  8, tid);
    }
    stage16(sb + SGW1F, (const char*)g_GW1F, 512, tid);
    stage16(sb + SGW2F, (const char*)g_GW2F, 64, tid);
    stage16(sb + SGB1, (const char*)Gb1, 16, tid);
    stage16(sb + SGB2, (const char*)Gb2, 2, tid);
    asm volatile("cp.async.commit_group;" ::: "memory");

    float x[16], ksum[16], kk[16];
    #pragma unroll
    for (int c = 0; c < 16; c++) kk[c] = 0.f;
    #pragma unroll
    for (int j = 0; j < 4; j++){
        float2 a = *(const float2*)(x0 + row0*32 + j*8 + 2*q);
        float2 b = *(const float2*)(x0 + (row0+8)*32 + j*8 + 2*q);
        x[j*4+0] = a.x; x[j*4+1] = a.y; x[j*4+2] = b.x; x[j*4+3] = b.y;
        if (half == 0){
            *(float2*)(out + row0*320 + j*8 + 2*q)     = a;
            *(float2*)(out + (row0+8)*320 + j*8 + 2*q) = b;
        }
    }

    asm volatile("cp.async.wait_group 0;" ::: "memory");
    __syncthreads();

    #pragma unroll 1
    for (int s = 0; s < TPTS - 1; s++){
        const float t0 = tspan[s], t1 = tspan[s+1];
        const float dt = t1 - t0;
        #pragma unroll
        for (int c = 0; c < 16; c++) ksum[c] = 0.f;

        #pragma unroll 1
        for (int sub = 0; sub < 4; sub++){
            const float nc   = (sub == 0) ? 0.f : ((sub == 3) ? dt : 0.5f*dt);
            const float tcur = t0 + nc;

            // pack xin A-fragments (k = 0..31) + t fragment (k=32..47)
            u32 XA[8], TF[4];
            #pragma unroll
            for (int jj = 0; jj < 2; jj++){
                int j0 = jj*2, j1 = jj*2+1;
                XA[jj*4+0] = f2h2(fmaf(nc, kk[j0*4+0], x[j0*4+0]), fmaf(nc, kk[j0*4+1], x[j0*4+1]));
                XA[jj*4+1] = f2h2(fmaf(nc, kk[j0*4+2], x[j0*4+2]), fmaf(nc, kk[j0*4+3], x[j0*4+3]));
                XA[jj*4+2] = f2h2(fmaf(nc, kk[j1*4+0], x[j1*4+0]), fmaf(nc, kk[j1*4+1], x[j1*4+1]));
                XA[jj*4+3] = f2h2(fmaf(nc, kk[j1*4+2], x[j1*4+2]), fmaf(nc, kk[j1*4+3], x[j1*4+3]));
            }
            {
                u32 th = (q == 0) ? f2h2(tcur, 0.f) : 0u;
                TF[0] = th; TF[1] = th; TF[2] = 0u; TF[3] = 0u;
            }

            __syncthreads();   // WAR: previous eval's combine done before F overwrite

            float dxs[16];
            #pragma unroll
            for (int c = 0; c < 16; c++) dxs[c] = 0.f;

            u32 HA[16];

            #pragma unroll 1
            for (int e = e0; e < e0 + 4; e++){
                const char* wb = smem + e * EXPW;

                // ---- L1: N=64, K=48 (X,X,T)
                float acc[32];
                #pragma unroll
                for (int j = 0; j < 8; j++){
                    uint2 bb;
                    bb = *(const uint2*)(wb + SW1F + (0*8+j)*256 + lane*8);
                    MMA4_INIT(&acc[j*4], XA[0],XA[1],XA[2],XA[3], bb);
                    bb = *(const uint2*)(wb + SW1F + (1*8+j)*256 + lane*8);
                    MMA4(&acc[j*4], XA[4],XA[5],XA[6],XA[7], bb);
                    bb = *(const uint2*)(wb + SW1F + (2*8+j)*256 + lane*8);
                    MMA4(&acc[j*4], TF[0],TF[1],TF[2],TF[3], bb);
                }
                EPI64(acc, wb + SB1, HA);

                // ---- L2: N=64, K=64
                #pragma unroll
                for (int j = 0; j < 8; j++){
                    uint2 bb = *(const uint2*)(wb + SW2F + (0*8+j)*256 + lane*8);
                    MMA4_INIT(&acc[j*4], HA[0],HA[1],HA[2],HA[3], bb);
                    #pragma unroll
                    for (int ks = 1; ks < 4; ks++){
                        bb = *(const uint2*)(wb + SW2F + (ks*8+j)*256 + lane*8);
                        MMA4(&acc[j*4], HA[ks*4+0],HA[ks*4+1],HA[ks*4+2],HA[ks*4+3], bb);
                    }
                }
                EPI64(acc, wb + SB2, HA);

                // ---- L3: N=32, K=64
                float a3[16];
                #pragma unroll
                for (int j = 0; j < 4; j++){
                    uint2 bb = *(const uint2*)(wb + SW3F + (0*4+j)*256 + lane*8);
                    MMA4_INIT(&a3[j*4], HA[0],HA[1],HA[2],HA[3], bb);
                    #pragma unroll
                    for (int ks = 1; ks < 4; ks++){
                        bb = *(const uint2*)(wb + SW3F + (ks*4+j)*256 + lane*8);
                        MMA4(&a3[j*4], HA[ks*4+0],HA[ks*4+1],HA[ks*4+2],HA[ks*4+3], bb);
                    }
                }
                {
                    const float* b3p = (const float*)(wb + SB3);
                    u32 fr[8];
                    #pragma unroll
                    for (int j = 0; j < 4; j++){
                        float2 bv = *(const float2*)(b3p + j*8 + 2*q);
                        float c0 = a3[j*4+0] + bv.x, c1 = a3[j*4+1] + bv.y;
                        float c2 = a3[j*4+2] + bv.x, c3 = a3[j*4+3] + bv.y;
                        dxs[j*4+0] += c0; dxs[j*4+1] += c1; dxs[j*4+2] += c2; dxs[j*4+3] += c3;
                        fr[j*2+0] = f2h2(c0, c1); fr[j*2+1] = f2h2(c2, c3);
                    }
                    uint4* fp = (uint4*)(smem + SFBASE + wlow*8192 + e*1024 + lane*32);
                    fp[0] = make_uint4(fr[0], fr[1], fr[2], fr[3]);
                    fp[1] = make_uint4(fr[4], fr[5], fr[6], fr[7]);
                }
            } // own 4 experts

            __syncthreads();   // RAW: both halves' F visible

            // add other half's experts to dxs (fp16-rounded F, gate input only)
            #pragma unroll
            for (int eo = 0; eo < 4; eo++){
                int e2 = (e0 ^ 4) + eo;
                const uint4* fp = (const uint4*)(smem + SFBASE + wlow*8192 + e2*1024 + lane*32);
                uint4 fa = fp[0], fb = fp[1];
                float2 t;
                t = h22f2(fa.x); dxs[0] += t.x; dxs[1] += t.y;
                t = h22f2(fa.y); dxs[2] += t.x; dxs[3] += t.y;
                t = h22f2(fa.z); dxs[4] += t.x; dxs[5] += t.y;
                t = h22f2(fa.w); dxs[6] += t.x; dxs[7] += t.y;
                t = h22f2(fb.x); dxs[8] += t.x; dxs[9] += t.y;
                t = h22f2(fb.y); dxs[10] += t.x; dxs[11] += t.y;
                t = h22f2(fb.z); dxs[12] += t.x; dxs[13] += t.y;
                t = h22f2(fb.w); dxs[14] += t.x; dxs[15] += t.y;
            }

            // ---- gating GEMM1 (redundant in both halves): A = [xin | dx_mean]
            u32 DXF[8];
            #pragma unroll
            for (int jj = 0; jj < 2; jj++){
                int j0 = jj*2, j1 = jj*2+1;
                DXF[jj*4+0] = f2h2(dxs[j0*4+0]*0.125f, dxs[j0*4+1]*0.125f);
                DXF[jj*4+1] = f2h2(dxs[j0*4+2]*0.125f, dxs[j0*4+3]*0.125f);
                DXF[jj*4+2] = f2h2(dxs[j1*4+0]*0.125f, dxs[j1*4+1]*0.125f);
                DXF[jj*4+3] = f2h2(dxs[j1*4+2]*0.125f, dxs[j1*4+3]*0.125f);
            }
            {
                float acc[32];
                #pragma unroll
                for (int j = 0; j < 8; j++){
                    uint2 bb;
                    bb = *(const uint2*)(smem + SGW1F + (0*8+j)*256 + lane*8);
                    MMA4_INIT(&acc[j*4], XA[0],XA[1],XA[2],XA[3], bb);
                    bb = *(const uint2*)(smem + SGW1F + (1*8+j)*256 + lane*8);
                    MMA4(&acc[j*4], XA[4],XA[5],XA[6],XA[7], bb);
                    bb = *(const uint2*)(smem + SGW1F + (2*8+j)*256 + lane*8);
                    MMA4(&acc[j*4], DXF[0],DXF[1],DXF[2],DXF[3], bb);
                    bb = *(const uint2*)(smem + SGW1F + (3*8+j)*256 + lane*8);
                    MMA4(&acc[j*4], DXF[4],DXF[5],DXF[6],DXF[7], bb);
                }
                EPI64(acc, smem + SGB1, HA);
            }
            // ---- gating GEMM2: N=8 logits + softmax
            float w0, w1, w80, w81;
            {
                float z[4];
                uint2 bb = *(const uint2*)(smem + SGW2F + 0*256 + lane*8);
                MMA4_INIT(z, HA[0],HA[1],HA[2],HA[3], bb);
                #pragma unroll
                for (int ks = 1; ks < 4; ks++){
                    bb = *(const uint2*)(smem + SGW2F + ks*256 + lane*8);
                    MMA4(z, HA[ks*4+0],HA[ks*4+1],HA[ks*4+2],HA[ks*4+3], bb);
                }
                float2 bv = *(const float2*)((const float*)(smem + SGB2) + 2*q);
                z[0] += bv.x; z[1] += bv.y; z[2] += bv.x; z[3] += bv.y;
                float m0 = fmaxf(z[0], z[1]);
                m0 = fmaxf(m0, __shfl_xor_sync(0xffffffffu, m0, 1));
                m0 = fmaxf(m0, __shfl_xor_sync(0xffffffffu, m0, 2));
                float e0v = exp_fast(z[0]-m0), e1v = exp_fast(z[1]-m0);
                float s0 = e0v + e1v;
                s0 += __shfl_xor_sync(0xffffffffu, s0, 1);
                s0 += __shfl_xor_sync(0xffffffffu, s0, 2);
                float i0 = rcp_fast(s0);
                w0 = e0v*i0; w1 = e1v*i0;
                float m1 = fmaxf(z[2], z[3]);
                m1 = fmaxf(m1, __shfl_xor_sync(0xffffffffu, m1, 1));
                m1 = fmaxf(m1, __shfl_xor_sync(0xffffffffu, m1, 2));
                float e2v = exp_fast(z[2]-m1), e3v = exp_fast(z[3]-m1);
                float s1 = e2v + e3v;
                s1 += __shfl_xor_sync(0xffffffffu, s1, 1);
                s1 += __shfl_xor_sync(0xffffffffu, s1, 2);
                float i1 = rcp_fast(s1);
                w80 = e2v*i1; w81 = e3v*i1;
            }
            // exchange expert weights within quad (lane q holds experts 2q,2q+1)
            float wA[8], wB[8];
            #pragma unroll
            for (int qq = 0; qq < 4; qq++){
                int src = (lane & ~3) | qq;
                wA[2*qq+0] = __shfl_sync(0xffffffffu, w0,  src);
                wA[2*qq+1] = __shfl_sync(0xffffffffu, w1,  src);
                wB[2*qq+0] = __shfl_sync(0xffffffffu, w80, src);
                wB[2*qq+1] = __shfl_sync(0xffffffffu, w81, src);
            }
            // combine k = sum_e wgt[e] * f_e (all 8 experts from smem)
            #pragma unroll
            for (int c = 0; c < 16; c++) kk[c] = 0.f;
            #pragma unroll
            for (int e2 = 0; e2 < 8; e2++){
                const uint4* fp = (const uint4*)(smem + SFBASE + wlow*8192 + e2*1024 + lane*32);
                uint4 fa = fp[0], fb = fp[1];
                float2 t;
                t = h22f2(fa.x); kk[0] = fmaf(wA[e2], t.x, kk[0]); kk[1] = fmaf(wA[e2], t.y, kk[1]);
                t = h22f2(fa.y); kk[2] = fmaf(wB[e2], t.x, kk[2]); kk[3] = fmaf(wB[e2], t.y, kk[3]);
                t = h22f2(fa.z); kk[4] = fmaf(wA[e2], t.x, kk[4]); kk[5] = fmaf(wA[e2], t.y, kk[5]);
                t = h22f2(fa.w); kk[6] = fmaf(wB[e2], t.x, kk[6]); kk[7] = fmaf(wB[e2], t.y, kk[7]);
                t = h22f2(fb.x); kk[8] = fmaf(wA[e2], t.x, kk[8]); kk[9] = fmaf(wA[e2], t.y, kk[9]);
                t = h22f2(fb.y); kk[10] = fmaf(wB[e2], t.x, kk[10]); kk[11] = fmaf(wB[e2], t.y, kk[11]);
                t = h22f2(fb.z); kk[12] = fmaf(wA[e2], t.x, kk[12]); kk[13] = fmaf(wA[e2], t.y, kk[13]);
                t = h22f2(fb.w); kk[14] = fmaf(wB[e2], t.x, kk[14]); kk[15] = fmaf(wB[e2], t.y, kk[15]);
            }
            const float ws = (sub == 0 || sub == 3) ? 1.f : 2.f;
            #pragma unroll
            for (int c = 0; c < 16; c++) ksum[c] = fmaf(ws, kk[c], ksum[c]);
        } // sub

        const float sc = dt * (1.f/6.f);
        #pragma unroll
        for (int c = 0; c < 16; c++) x[c] = fmaf(sc, ksum[c], x[c]);
        if (half == 0){
            #pragma unroll
            for (int j = 0; j < 4; j++){
                *(float2*)(out + row0*320 + (s+1)*32 + j*8 + 2*q)     = make_float2(x[j*4+0], x[j*4+1]);
                *(float2*)(out + (row0+8)*320 + (s+1)*32 + j*8 + 2*q) = make_float2(x[j*4+2], x[j*4+3]);
            }
        }
    } // step
}

extern "C" void kernel_launch(void* const* d_in, const int* in_sizes, int n_in,
                              void* d_out, int out_size)
{
    (void)in_sizes; (void)n_in; (void)out_size;
    conv_weights<<<128, 256>>>(
        (const float*)d_in[2],  (const float*)d_in[4], (const float*)d_in[6],
        (const float*)d_in[8],  (const float*)d_in[10]);
    cudaFuncSetAttribute(ameode_mma, cudaFuncAttributeMaxDynamicSharedMemorySize, SMEM_BYTES);
    ameode_mma<<<128, CTA, SMEM_BYTES>>>(
        (const float*)d_in[0],  (const float*)d_in[1],
        (const float*)d_in[3],  (const float*)d_in[5], (const float*)d_in[7],
        (const float*)d_in[9],  (const float*)d_in[11],
        (float*)d_out);
}

// round 16
// speedup vs baseline: 1.2234x; 1.2234x over previous
#include <cuda_runtime.h>
#include <cuda_fp16.h>

typedef unsigned int u32;

#define TPTS 10
#define CTA 128

// ---- smem byte offsets ----
// 8 resident expert buffers, stride 17280:
#define EXPW   17280
#define SW1F   0          // 2 ksteps * 8 j * 256B = 4096
#define SW2F   4096       // 8192
#define SW3F   12288      // 4096
#define SW1T33 16384      // 256  (W1 row-32 as f32, for scalar t-term)
#define SB1    16640      // 256
#define SB2    16896      // 256
#define SB3    17152      // 128
#define SGW1F  138240     // 8192
#define SGW2F  146432     // 1024
#define SGB1   147456     // 256
#define SGB2   147712     // 32
#define SFBASE 147744     // F[warp][e][rg][lane][32B] = 4*8*2*32*32 = 65536
#define SMEM_BYTES 213280

// weights pre-arranged in B-fragment register order
__device__ __align__(16) u32   g_W1F[8*2*8*64];
__device__ __align__(16) float g_W1T33[8*64];
__device__ __align__(16) u32   g_W2F[8*4*8*64];
__device__ __align__(16) u32   g_W3F[8*4*4*64];
__device__ __align__(16) u32   g_GW1F[4*8*64];
__device__ __align__(16) u32   g_GW2F[4*64];

static __device__ __forceinline__ u32 f2h2(float lo, float hi){
    u32 r; asm("cvt.rn.f16x2.f32 %0, %2, %1;" : "=r"(r) : "f"(lo), "f"(hi)); return r;
}
static __device__ __forceinline__ float2 h22f2(u32 h){
    __half2 v = *(__half2*)&h; return __half22float2(v);
}
static __device__ __forceinline__ u32 tanh_h2(u32 h){
    u32 r; asm("tanh.approx.f16x2 %0,%1;" : "=r"(r) : "r"(h)); return r;
}
static __device__ __forceinline__ float exp_fast(float x){
    float e; asm("ex2.approx.f32 %0,%1;" : "=f"(e) : "f"(x * 1.4426950408889634f)); return e;
}
static __device__ __forceinline__ float rcp_fast(float x){
    float r; asm("rcp.approx.f32 %0,%1;" : "=f"(r) : "f"(x)); return r;
}

#define MMA4(d, a0,a1,a2,a3, b) \
    asm volatile("mma.sync.aligned.m16n8k16.row.col.f32.f16.f16.f32 " \
        "{%0,%1,%2,%3},{%4,%5,%6,%7},{%8,%9},{%0,%1,%2,%3};" \
        : "+f"((d)[0]),"+f"((d)[1]),"+f"((d)[2]),"+f"((d)[3]) \
        : "r"(a0),"r"(a1),"r"(a2),"r"(a3),"r"((b).x),"r"((b).y))

#define MMA4_INIT(d, a0,a1,a2,a3, b) \
    asm volatile("mma.sync.aligned.m16n8k16.row.col.f32.f16.f16.f32 " \
        "{%0,%1,%2,%3},{%4,%5,%6,%7},{%8,%9},{%10,%10,%10,%10};" \
        : "=f"((d)[0]),"=f"((d)[1]),"=f"((d)[2]),"=f"((d)[3]) \
        : "r"(a0),"r"(a1),"r"(a2),"r"(a3),"r"((b).x),"r"((b).y),"f"(0.f))

static __device__ __forceinline__ void stage16(u32 dst, const char* src, int n16, int tid){
    for (int i = tid; i < n16; i += CTA)
        asm volatile("cp.async.cg.shared.global [%0],[%1],16;"
                     :: "r"(dst + (u32)i*16), "l"(src + i*16));
}

// dual-rowgroup epilogue: bias (shared load) -> fp16 pack -> tanh.f16x2
#define EPI64D(acc, biasptr, HA) { \
    const float* _b = (const float*)(biasptr); \
    _Pragma("unroll") \
    for (int j = 0; j < 8; j++){ \
        float2 bv = *(const float2*)(_b + j*8 + 2*q); \
        int hi_ = (j>>1)*4 + (j&1)*2; \
        (HA)[hi_+0]    = tanh_h2(f2h2((acc)[j*4+0] + bv.x, (acc)[j*4+1] + bv.y)); \
        (HA)[hi_+1]    = tanh_h2(f2h2((acc)[j*4+2] + bv.x, (acc)[j*4+3] + bv.y)); \
        (HA)[16+hi_+0] = tanh_h2(f2h2((acc)[32+j*4+0] + bv.x, (acc)[32+j*4+1] + bv.y)); \
        (HA)[16+hi_+1] = tanh_h2(f2h2((acc)[32+j*4+2] + bv.x, (acc)[32+j*4+3] + bv.y)); \
    } }

// ---------------- weight frag-order pre-kernel ----------------
__global__ void conv_weights(const float* __restrict__ W1, const float* __restrict__ W2,
                             const float* __restrict__ W3, const float* __restrict__ Gw1,
                             const float* __restrict__ Gw2){
    int i0 = blockIdx.x*blockDim.x + threadIdx.x, st = gridDim.x*blockDim.x;
    for (int i = i0; i < 8*2*8*64; i += st){
        int r = i & 1, t = i >> 1, l = t & 31; t >>= 5;
        int j = t & 7; t >>= 3; int ks = t & 1, e = t >> 1;
        int k = ks*16 + (l&3)*2 + r*8, n = j*8 + (l>>2);   // k in [0,31] < 33 always
        __half2 h = __floats2half2_rn(W1[e*2112 + k*64 + n], W1[e*2112 + (k+1)*64 + n]);
        g_W1F[i] = *(u32*)&h;
    }
    for (int i = i0; i < 8*64; i += st){
        int e = i >> 6, n = i & 63;
        g_W1T33[i] = W1[e*2112 + 32*64 + n];
    }
    for (int i = i0; i < 8*4*8*64; i += st){
        int r = i & 1, t = i >> 1, l = t & 31; t >>= 5;
        int j = t & 7; t >>= 3; int ks = t & 3, e = t >> 2;
        int k = ks*16 + (l&3)*2 + r*8, n = j*8 + (l>>2);
        __half2 h = __floats2half2_rn(W2[e*4096 + k*64 + n], W2[e*4096 + (k+1)*64 + n]);
        g_W2F[i] = *(u32*)&h;
    }
    for (int i = i0; i < 8*4*4*64; i += st){
        int r = i & 1, t = i >> 1, l = t & 31; t >>= 5;
        int j = t & 3; t >>= 2; int ks = t & 3, e = t >> 2;
        int k = ks*16 + (l&3)*2 + r*8, n = j*8 + (l>>2);
        __half2 h = __floats2half2_rn(W3[e*2048 + k*32 + n], W3[e*2048 + (k+1)*32 + n]);
        g_W3F[i] = *(u32*)&h;
    }
    for (int i = i0; i < 4*8*64; i += st){
        int r = i & 1, t = i >> 1, l = t & 31; t >>= 5;
        int j = t & 7, ks = t >> 3;
        int k = ks*16 + (l&3)*2 + r*8, n = j*8 + (l>>2);
        __half2 h = __floats2half2_rn(Gw1[k*64 + n], Gw1[(k+1)*64 + n]);
        g_GW1F[i] = *(u32*)&h;
    }
    for (int i = i0; i < 4*64; i += st){
        int r = i & 1, t = i >> 1, l = t & 31; t >>= 5;
        int ks = t;
        int k = ks*16 + (l&3)*2 + r*8, n = l >> 2;
        __half2 h = __floats2half2_rn(Gw2[k*8 + n], Gw2[(k+1)*8 + n]);
        g_GW2F[i] = *(u32*)&h;
    }
}

// ---------------- main kernel ----------------
// 4 warps x 32 rows: warp owns rowgroups rg0 (base+g, +8) and rg1 (base+16+g, +8).
// Every B-frag load feeds both rowgroups' MMAs.
__global__ void __launch_bounds__(CTA, 1)
ameode_mma(const float* __restrict__ x0, const float* __restrict__ tspan,
           const float* __restrict__ b1, const float* __restrict__ b2, const float* __restrict__ b3,
           const float* __restrict__ Gb1, const float* __restrict__ Gb2,
           float* __restrict__ out)
{
    extern __shared__ char smem[];
    u32 sb = (u32)__cvta_generic_to_shared(smem);
    const int tid = threadIdx.x, lane = tid & 31, warp = tid >> 5;
    const int g = lane >> 2, q = lane & 3;
    const int r0 = blockIdx.x*128 + warp*32 + g;   // rg0: rows r0, r0+8 ; rg1: +16, +24

    // stage ALL weights ONCE
    #pragma unroll 1
    for (int e = 0; e < 8; e++){
        u32 bo = sb + (u32)e * EXPW;
        stage16(bo + SW1F,   (const char*)g_W1F + e*4096, 256, tid);
        stage16(bo + SW2F,   (const char*)g_W2F + e*8192, 512, tid);
        stage16(bo + SW3F,   (const char*)g_W3F + e*4096, 256, tid);
        stage16(bo + SW1T33, (const char*)(g_W1T33 + e*64), 16, tid);
        stage16(bo + SB1, (const char*)(b1 + e*64), 16, tid);
        stage16(bo + SB2, (const char*)(b2 + e*64), 16, tid);
        stage16(bo + SB3, (const char*)(b3 + e*32),  8, tid);
    }
    stage16(sb + SGW1F, (const char*)g_GW1F, 512, tid);
    stage16(sb + SGW2F, (const char*)g_GW2F, 64, tid);
    stage16(sb + SGB1, (const char*)Gb1, 16, tid);
    stage16(sb + SGB2, (const char*)Gb2, 2, tid);
    asm volatile("cp.async.commit_group;" ::: "memory");

    float x[32], ksum[32], kk[32];
    #pragma unroll
    for (int c = 0; c < 32; c++) kk[c] = 0.f;
    #pragma unroll
    for (int rg = 0; rg < 2; rg++){
        int ra = r0 + rg*16;
        #pragma unroll
        for (int j = 0; j < 4; j++){
            float2 a = *(const float2*)(x0 + ra*32 + j*8 + 2*q);
            float2 b = *(const float2*)(x0 + (ra+8)*32 + j*8 + 2*q);
            x[rg*16+j*4+0] = a.x; x[rg*16+j*4+1] = a.y;
            x[rg*16+j*4+2] = b.x; x[rg*16+j*4+3] = b.y;
            *(float2*)(out + ra*320 + j*8 + 2*q)     = a;
            *(float2*)(out + (ra+8)*320 + j*8 + 2*q) = b;
        }
    }

    asm volatile("cp.async.wait_group 0;" ::: "memory");
    __syncthreads();   // the ONLY CTA-wide barrier

    #pragma unroll 1
    for (int s = 0; s < TPTS - 1; s++){
        const float t0 = tspan[s], t1 = tspan[s+1];
        const float dt = t1 - t0;
        #pragma unroll
        for (int c = 0; c < 32; c++) ksum[c] = 0.f;

        #pragma unroll 1
        for (int sub = 0; sub < 4; sub++){
            const float nc   = (sub == 0) ? 0.f : ((sub == 3) ? dt : 0.5f*dt);
            const float tcur = t0 + nc;

            // pack xin A-fragments per rowgroup
            u32 XA[16];
            #pragma unroll
            for (int rg = 0; rg < 2; rg++){
                #pragma unroll
                for (int jj = 0; jj < 2; jj++){
                    int j0 = jj*2, j1 = jj*2+1, o = rg*16;
                    XA[rg*8+jj*4+0] = f2h2(fmaf(nc, kk[o+j0*4+0], x[o+j0*4+0]), fmaf(nc, kk[o+j0*4+1], x[o+j0*4+1]));
                    XA[rg*8+jj*4+1] = f2h2(fmaf(nc, kk[o+j0*4+2], x[o+j0*4+2]), fmaf(nc, kk[o+j0*4+3], x[o+j0*4+3]));
                    XA[rg*8+jj*4+2] = f2h2(fmaf(nc, kk[o+j1*4+0], x[o+j1*4+0]), fmaf(nc, kk[o+j1*4+1], x[o+j1*4+1]));
                    XA[rg*8+jj*4+3] = f2h2(fmaf(nc, kk[o+j1*4+2], x[o+j1*4+2]), fmaf(nc, kk[o+j1*4+3], x[o+j1*4+3]));
                }
            }

            float dxs[32];
            #pragma unroll
            for (int c = 0; c < 32; c++) dxs[c] = 0.f;

            u32 HA[32];
            float acc[64];

            #pragma unroll 1
            for (int e = 0; e < 8; e++){
                const char* wb = smem + e * EXPW;

                // ---- L1: N=64, K=32 MMA + scalar t-term
                #pragma unroll
                for (int j = 0; j < 8; j++){
                    uint2 bb = *(const uint2*)(wb + SW1F + j*256 + lane*8);
                    MMA4_INIT(&acc[j*4],    XA[0],XA[1],XA[2],XA[3], bb);
                    MMA4_INIT(&acc[32+j*4], XA[8],XA[9],XA[10],XA[11], bb);
                    bb = *(const uint2*)(wb + SW1F + (8+j)*256 + lane*8);
                    MMA4(&acc[j*4],    XA[4],XA[5],XA[6],XA[7], bb);
                    MMA4(&acc[32+j*4], XA[12],XA[13],XA[14],XA[15], bb);
                    float2 w33 = *(const float2*)(wb + SW1T33 + (j*8 + 2*q)*4);
                    float tw0 = tcur*w33.x, tw1 = tcur*w33.y;
                    acc[j*4+0] += tw0; acc[j*4+1] += tw1; acc[j*4+2] += tw0; acc[j*4+3] += tw1;
                    acc[32+j*4+0] += tw0; acc[32+j*4+1] += tw1; acc[32+j*4+2] += tw0; acc[32+j*4+3] += tw1;
                }
                EPI64D(acc, wb + SB1, HA);

                // ---- L2: N=64, K=64
                #pragma unroll
                for (int j = 0; j < 8; j++){
                    uint2 bb = *(const uint2*)(wb + SW2F + (0*8+j)*256 + lane*8);
                    MMA4_INIT(&acc[j*4],    HA[0],HA[1],HA[2],HA[3], bb);
                    MMA4_INIT(&acc[32+j*4], HA[16],HA[17],HA[18],HA[19], bb);
                    #pragma unroll
                    for (int ks = 1; ks < 4; ks++){
                        bb = *(const uint2*)(wb + SW2F + (ks*8+j)*256 + lane*8);
                        MMA4(&acc[j*4],    HA[ks*4+0],HA[ks*4+1],HA[ks*4+2],HA[ks*4+3], bb);
                        MMA4(&acc[32+j*4], HA[16+ks*4+0],HA[16+ks*4+1],HA[16+ks*4+2],HA[16+ks*4+3], bb);
                    }
                }
                EPI64D(acc, wb + SB2, HA);

                // ---- L3: N=32, K=64 (uses acc[0..15] / acc[32..47])
                #pragma unroll
                for (int j = 0; j < 4; j++){
                    uint2 bb = *(const uint2*)(wb + SW3F + (0*4+j)*256 + lane*8);
                    MMA4_INIT(&acc[j*4],    HA[0],HA[1],HA[2],HA[3], bb);
                    MMA4_INIT(&acc[32+j*4], HA[16],HA[17],HA[18],HA[19], bb);
                    #pragma unroll
                    for (int ks = 1; ks < 4; ks++){
                        bb = *(const uint2*)(wb + SW3F + (ks*4+j)*256 + lane*8);
                        MMA4(&acc[j*4],    HA[ks*4+0],HA[ks*4+1],HA[ks*4+2],HA[ks*4+3], bb);
                        MMA4(&acc[32+j*4], HA[16+ks*4+0],HA[16+ks*4+1],HA[16+ks*4+2],HA[16+ks*4+3], bb);
                    }
                }
                {
                    const float* b3p = (const float*)(wb + SB3);
                    u32 fr0[8], fr1[8];
                    #pragma unroll
                    for (int j = 0; j < 4; j++){
                        float2 bv = *(const float2*)(b3p + j*8 + 2*q);
                        float c0 = acc[j*4+0] + bv.x, c1 = acc[j*4+1] + bv.y;
                        float c2 = acc[j*4+2] + bv.x, c3 = acc[j*4+3] + bv.y;
                        dxs[j*4+0] += c0; dxs[j*4+1] += c1; dxs[j*4+2] += c2; dxs[j*4+3] += c3;
                        fr0[j*2+0] = f2h2(c0, c1); fr0[j*2+1] = f2h2(c2, c3);
                        float d0 = acc[32+j*4+0] + bv.x, d1 = acc[32+j*4+1] + bv.y;
                        float d2 = acc[32+j*4+2] + bv.x, d3 = acc[32+j*4+3] + bv.y;
                        dxs[16+j*4+0] += d0; dxs[16+j*4+1] += d1; dxs[16+j*4+2] += d2; dxs[16+j*4+3] += d3;
                        fr1[j*2+0] = f2h2(d0, d1); fr1[j*2+1] = f2h2(d2, d3);
                    }
                    uint4* fp0 = (uint4*)(smem + SFBASE + warp*16384 + e*2048 + lane*32);
                    fp0[0] = make_uint4(fr0[0], fr0[1], fr0[2], fr0[3]);
                    fp0[1] = make_uint4(fr0[4], fr0[5], fr0[6], fr0[7]);
                    uint4* fp1 = (uint4*)(smem + SFBASE + warp*16384 + e*2048 + 1024 + lane*32);
                    fp1[0] = make_uint4(fr1[0], fr1[1], fr1[2], fr1[3]);
                    fp1[1] = make_uint4(fr1[4], fr1[5], fr1[6], fr1[7]);
                }
            } // experts

            // ---- gating GEMM1: A = [xin | dx_mean], N=64, K=64
            u32 DXF[16];
            #pragma unroll
            for (int rg = 0; rg < 2; rg++){
                #pragma unroll
                for (int jj = 0; jj < 2; jj++){
                    int j0 = jj*2, j1 = jj*2+1, o = rg*16;
                    DXF[rg*8+jj*4+0] = f2h2(dxs[o+j0*4+0]*0.125f, dxs[o+j0*4+1]*0.125f);
                    DXF[rg*8+jj*4+1] = f2h2(dxs[o+j0*4+2]*0.125f, dxs[o+j0*4+3]*0.125f);
                    DXF[rg*8+jj*4+2] = f2h2(dxs[o+j1*4+0]*0.125f, dxs[o+j1*4+1]*0.125f);
                    DXF[rg*8+jj*4+3] = f2h2(dxs[o+j1*4+2]*0.125f, dxs[o+j1*4+3]*0.125f);
                }
            }
            #pragma unroll
            for (int j = 0; j < 8; j++){
                uint2 bb;
                bb = *(const uint2*)(smem + SGW1F + (0*8+j)*256 + lane*8);
                MMA4_INIT(&acc[j*4],    XA[0],XA[1],XA[2],XA[3], bb);
                MMA4_INIT(&acc[32+j*4], XA[8],XA[9],XA[10],XA[11], bb);
                bb = *(const uint2*)(smem + SGW1F + (1*8+j)*256 + lane*8);
                MMA4(&acc[j*4],    XA[4],XA[5],XA[6],XA[7], bb);
                MMA4(&acc[32+j*4], XA[12],XA[13],XA[14],XA[15], bb);
                bb = *(const uint2*)(smem + SGW1F + (2*8+j)*256 + lane*8);
                MMA4(&acc[j*4],    DXF[0],DXF[1],DXF[2],DXF[3], bb);
                MMA4(&acc[32+j*4], DXF[8],DXF[9],DXF[10],DXF[11], bb);
                bb = *(const uint2*)(smem + SGW1F + (3*8+j)*256 + lane*8);
                MMA4(&acc[j*4],    DXF[4],DXF[5],DXF[6],DXF[7], bb);
                MMA4(&acc[32+j*4], DXF[12],DXF[13],DXF[14],DXF[15], bb);
            }
            EPI64D(acc, smem + SGB1, HA);

            // ---- gating GEMM2: N=8 logits (both rowgroups share bb)
            float zv[8];
            {
                uint2 bb = *(const uint2*)(smem + SGW2F + 0*256 + lane*8);
                MMA4_INIT(&zv[0], HA[0],HA[1],HA[2],HA[3], bb);
                MMA4_INIT(&zv[4], HA[16],HA[17],HA[18],HA[19], bb);
                #pragma unroll
                for (int ks = 1; ks < 4; ks++){
                    bb = *(const uint2*)(smem + SGW2F + ks*256 + lane*8);
                    MMA4(&zv[0], HA[ks*4+0],HA[ks*4+1],HA[ks*4+2],HA[ks*4+3], bb);
                    MMA4(&zv[4], HA[16+ks*4+0],HA[16+ks*4+1],HA[16+ks*4+2],HA[16+ks*4+3], bb);
                }
            }
            float wA[16], wB[16];
            float2 bvz = *(const float2*)((const float*)(smem + SGB2) + 2*q);
            #pragma unroll
            for (int rg = 0; rg < 2; rg++){
                float* z = &zv[rg*4];
                z[0] += bvz.x; z[1] += bvz.y; z[2] += bvz.x; z[3] += bvz.y;
                float m0 = fmaxf(z[0], z[1]);
                m0 = fmaxf(m0, __shfl_xor_sync(0xffffffffu, m0, 1));
                m0 = fmaxf(m0, __shfl_xor_sync(0xffffffffu, m0, 2));
                float e0v = exp_fast(z[0]-m0), e1v = exp_fast(z[1]-m0);
                float s0 = e0v + e1v;
                s0 += __shfl_xor_sync(0xffffffffu, s0, 1);
                s0 += __shfl_xor_sync(0xffffffffu, s0, 2);
                float i0 = rcp_fast(s0);
                float w0 = e0v*i0, w1 = e1v*i0;
                float m1 = fmaxf(z[2], z[3]);
                m1 = fmaxf(m1, __shfl_xor_sync(0xffffffffu, m1, 1));
                m1 = fmaxf(m1, __shfl_xor_sync(0xffffffffu, m1, 2));
                float e2v = exp_fast(z[2]-m1), e3v = exp_fast(z[3]-m1);
                float s1 = e2v + e3v;
                s1 += __shfl_xor_sync(0xffffffffu, s1, 1);
                s1 += __shfl_xor_sync(0xffffffffu, s1, 2);
                float i1 = rcp_fast(s1);
                float w80 = e2v*i1, w81 = e3v*i1;
                #pragma unroll
                for (int qq = 0; qq < 4; qq++){
                    int src = (lane & ~3) | qq;
                    wA[rg*8+2*qq+0] = __shfl_sync(0xffffffffu, w0,  src);
                    wA[rg*8+2*qq+1] = __shfl_sync(0xffffffffu, w1,  src);
                    wB[rg*8+2*qq+0] = __shfl_sync(0xffffffffu, w80, src);
                    wB[rg*8+2*qq+1] = __shfl_sync(0xffffffffu, w81, src);
                }
            }

            // ---- combine k = sum_e wgt[e] * f_e
            #pragma unroll
            for (int c = 0; c < 32; c++) kk[c] = 0.f;
            #pragma unroll
            for (int rg = 0; rg < 2; rg++){
                int o = rg*16;
                #pragma unroll
                for (int e2 = 0; e2 < 8; e2++){
                    const uint4* fp = (const uint4*)(smem + SFBASE + warp*16384 + e2*2048 + rg*1024 + lane*32);
                    uint4 fa = fp[0], fb = fp[1];
                    float va = wA[rg*8+e2], vb = wB[rg*8+e2];
                    float2 t;
                    t = h22f2(fa.x); kk[o+0] = fmaf(va, t.x, kk[o+0]); kk[o+1] = fmaf(va, t.y, kk[o+1]);
                    t = h22f2(fa.y); kk[o+2] = fmaf(vb, t.x, kk[o+2]); kk[o+3] = fmaf(vb, t.y, kk[o+3]);
                    t = h22f2(fa.z); kk[o+4] = fmaf(va, t.x, kk[o+4]); kk[o+5] = fmaf(va, t.y, kk[o+5]);
                    t = h22f2(fa.w); kk[o+6] = fmaf(vb, t.x, kk[o+6]); kk[o+7] = fmaf(vb, t.y, kk[o+7]);
                    t = h22f2(fb.x); kk[o+8] = fmaf(va, t.x, kk[o+8]); kk[o+9] = fmaf(va, t.y, kk[o+9]);
                    t = h22f2(fb.y); kk[o+10] = fmaf(vb, t.x, kk[o+10]); kk[o+11] = fmaf(vb, t.y, kk[o+11]);
                    t = h22f2(fb.z); kk[o+12] = fmaf(va, t.x, kk[o+12]); kk[o+13] = fmaf(va, t.y, kk[o+13]);
                    t = h22f2(fb.w); kk[o+14] = fmaf(vb, t.x, kk[o+14]); kk[o+15] = fmaf(vb, t.y, kk[o+15]);
                }
            }
            const float ws = (sub == 0 || sub == 3) ? 1.f : 2.f;
            #pragma unroll
            for (int c = 0; c < 32; c++) ksum[c] = fmaf(ws, kk[c], ksum[c]);
        } // sub

        const float sc = dt * (1.f/6.f);
        #pragma unroll
        for (int c = 0; c < 32; c++) x[c] = fmaf(sc, ksum[c], x[c]);
        #pragma unroll
        for (int rg = 0; rg < 2; rg++){
            int ra = r0 + rg*16, o = rg*16;
            #pragma unroll
            for (int j = 0; j < 4; j++){
                *(float2*)(out + ra*320 + (s+1)*32 + j*8 + 2*q)     = make_float2(x[o+j*4+0], x[o+j*4+1]);
                *(float2*)(out + (ra+8)*320 + (s+1)*32 + j*8 + 2*q) = make_float2(x[o+j*4+2], x[o+j*4+3]);
            }
        }
    } // step
}

extern "C" void kernel_launch(void* const* d_in, const int* in_sizes, int n_in,
                              void* d_out, int out_size)
{
    (void)in_sizes; (void)n_in; (void)out_size;
    conv_weights<<<128, 256>>>(
        (const float*)d_in[2],  (const float*)d_in[4], (const float*)d_in[6],
        (const float*)d_in[8],  (const float*)d_in[10]);
    cudaFuncSetAttribute(ameode_mma, cudaFuncAttributeMaxDynamicSharedMemorySize, SMEM_BYTES);
    ameode_mma<<<128, CTA, SMEM_BYTES>>>(
        (const float*)d_in[0],  (const float*)d_in[1],
        (const float*)d_in[3],  (const float*)d_in[5], (const float*)d_in[7],
        (const float*)d_in[9],  (const float*)d_in[11],
        (float*)d_out);
}

// round 17
// speedup vs baseline: 1.3566x; 1.1089x over previous
#include <cuda_runtime.h>
#include <cuda_fp16.h>

typedef unsigned int u32;

#define TPTS 10
#define CTA 256

// ---- smem byte offsets ----
// 8 resident expert buffers, stride 17280:
#define EXPW   17280
#define SW1F   0          // 2 ksteps * 8 j * 256B = 4096
#define SW2F   4096       // 8192
#define SW3F   12288      // 4096
#define SW1T33 16384      // 256  (W1 row-32 as f32, scalar t-term)
#define SB1    16640      // 256
#define SB2    16896      // 256
#define SB3    17152      // 128
#define SGW1F  138240     // 8192
#define SGW2F  146432     // 1024
#define SGB1   147456     // 256
#define SGB2   147712     // 32
#define SMEM_BYTES 147744

// weights pre-arranged in B-fragment register order
__device__ __align__(16) u32   g_W1F[8*2*8*64];
__device__ __align__(16) float g_W1T33[8*64];
__device__ __align__(16) u32   g_W2F[8*4*8*64];
__device__ __align__(16) u32   g_W3F[8*4*4*64];
__device__ __align__(16) u32   g_GW1F[4*8*64];
__device__ __align__(16) u32   g_GW2F[4*64];

static __device__ __forceinline__ u32 f2h2(float lo, float hi){
    u32 r; asm("cvt.rn.f16x2.f32 %0, %2, %1;" : "=r"(r) : "f"(lo), "f"(hi)); return r;
}
static __device__ __forceinline__ float2 h22f2(u32 h){
    __half2 v = *(__half2*)&h; return __half22float2(v);
}
static __device__ __forceinline__ u32 tanh_h2(u32 h){
    u32 r; asm("tanh.approx.f16x2 %0,%1;" : "=r"(r) : "r"(h)); return r;
}
static __device__ __forceinline__ float exp_fast(float x){
    float e; asm("ex2.approx.f32 %0,%1;" : "=f"(e) : "f"(x * 1.4426950408889634f)); return e;
}
static __device__ __forceinline__ float rcp_fast(float x){
    float r; asm("rcp.approx.f32 %0,%1;" : "=f"(r) : "f"(x)); return r;
}

#define MMA4(d, a0,a1,a2,a3, b) \
    asm volatile("mma.sync.aligned.m16n8k16.row.col.f32.f16.f16.f32 " \
        "{%0,%1,%2,%3},{%4,%5,%6,%7},{%8,%9},{%0,%1,%2,%3};" \
        : "+f"((d)[0]),"+f"((d)[1]),"+f"((d)[2]),"+f"((d)[3]) \
        : "r"(a0),"r"(a1),"r"(a2),"r"(a3),"r"((b).x),"r"((b).y))

#define MMA4_INIT(d, a0,a1,a2,a3, b) \
    asm volatile("mma.sync.aligned.m16n8k16.row.col.f32.f16.f16.f32 " \
        "{%0,%1,%2,%3},{%4,%5,%6,%7},{%8,%9},{%10,%10,%10,%10};" \
        : "=f"((d)[0]),"=f"((d)[1]),"=f"((d)[2]),"=f"((d)[3]) \
        : "r"(a0),"r"(a1),"r"(a2),"r"(a3),"r"((b).x),"r"((b).y),"f"(0.f))

static __device__ __forceinline__ void stage16(u32 dst, const char* src, int n16, int tid){
    for (int i = tid; i < n16; i += CTA)
        asm volatile("cp.async.cg.shared.global [%0],[%1],16;"
                     :: "r"(dst + (u32)i*16), "l"(src + i*16));
}

// epilogue: bias add (fp32) -> fp16 pack -> tanh.f16x2 -> A-frags
#define EPI64(acc, biasptr, HA) { \
    const float* _b = (const float*)(biasptr); \
    _Pragma("unroll") \
    for (int j = 0; j < 8; j++){ \
        float2 bv = *(const float2*)(_b + j*8 + 2*q); \
        u32 p0 = f2h2((acc)[j*4+0] + bv.x, (acc)[j*4+1] + bv.y); \
        u32 p1 = f2h2((acc)[j*4+2] + bv.x, (acc)[j*4+3] + bv.y); \
        (HA)[(j>>1)*4 + (j&1)*2 + 0] = tanh_h2(p0); \
        (HA)[(j>>1)*4 + (j&1)*2 + 1] = tanh_h2(p1); \
    } }

// ---------------- weight frag-order pre-kernel ----------------
__global__ void conv_weights(const float* __restrict__ W1, const float* __restrict__ W2,
                             const float* __restrict__ W3, const float* __restrict__ Gw1,
                             const float* __restrict__ Gw2){
    int i0 = blockIdx.x*blockDim.x + threadIdx.x, st = gridDim.x*blockDim.x;
    for (int i = i0; i < 8*2*8*64; i += st){
        int r = i & 1, t = i >> 1, l = t & 31; t >>= 5;
        int j = t & 7; t >>= 3; int ks = t & 1, e = t >> 1;
        int k = ks*16 + (l&3)*2 + r*8, n = j*8 + (l>>2);
        __half2 h = __floats2half2_rn(W1[e*2112 + k*64 + n], W1[e*2112 + (k+1)*64 + n]);
        g_W1F[i] = *(u32*)&h;
    }
    for (int i = i0; i < 8*64; i += st){
        int e = i >> 6, n = i & 63;
        g_W1T33[i] = W1[e*2112 + 32*64 + n];
    }
    for (int i = i0; i < 8*4*8*64; i += st){
        int r = i & 1, t = i >> 1, l = t & 31; t >>= 5;
        int j = t & 7; t >>= 3; int ks = t & 3, e = t >> 2;
        int k = ks*16 + (l&3)*2 + r*8, n = j*8 + (l>>2);
        __half2 h = __floats2half2_rn(W2[e*4096 + k*64 + n], W2[e*4096 + (k+1)*64 + n]);
        g_W2F[i] = *(u32*)&h;
    }
    for (int i = i0; i < 8*4*4*64; i += st){
        int r = i & 1, t = i >> 1, l = t & 31; t >>= 5;
        int j = t & 3; t >>= 2; int ks = t & 3, e = t >> 2;
        int k = ks*16 + (l&3)*2 + r*8, n = j*8 + (l>>2);
        __half2 h = __floats2half2_rn(W3[e*2048 + k*32 + n], W3[e*2048 + (k+1)*32 + n]);
        g_W3F[i] = *(u32*)&h;
    }
    for (int i = i0; i < 4*8*64; i += st){
        int r = i & 1, t = i >> 1, l = t & 31; t >>= 5;
        int j = t & 7, ks = t >> 3;
        int k = ks*16 + (l&3)*2 + r*8, n = j*8 + (l>>2);
        __half2 h = __floats2half2_rn(Gw1[k*64 + n], Gw1[(k+1)*64 + n]);
        g_GW1F[i] = *(u32*)&h;
    }
    for (int i = i0; i < 4*64; i += st){
        int r = i & 1, t = i >> 1, l = t & 31; t >>= 5;
        int ks = t;
        int k = ks*16 + (l&3)*2 + r*8, n = l >> 2;
        __half2 h = __floats2half2_rn(Gw2[k*8 + n], Gw2[(k+1)*8 + n]);
        g_GW2F[i] = *(u32*)&h;
    }
}

// ---------------- main kernel ----------------
// 8 warps x 16 rows (R14 skeleton); F kept in registers; t-term scalar.
__global__ void __launch_bounds__(CTA, 1)
ameode_mma(const float* __restrict__ x0, const float* __restrict__ tspan,
           const float* __restrict__ b1, const float* __restrict__ b2, const float* __restrict__ b3,
           const float* __restrict__ Gb1, const float* __restrict__ Gb2,
           float* __restrict__ out)
{
    extern __shared__ char smem[];
    u32 sb = (u32)__cvta_generic_to_shared(smem);
    const int tid = threadIdx.x, lane = tid & 31, warp = tid >> 5;
    const int g = lane >> 2, q = lane & 3;
    const int row0 = blockIdx.x*128 + warp*16 + g;    // rows row0, row0+8

    // stage ALL weights ONCE
    #pragma unroll 1
    for (int e = 0; e < 8; e++){
        u32 bo = sb + (u32)e * EXPW;
        stage16(bo + SW1F,   (const char*)g_W1F + e*4096, 256, tid);
        stage16(bo + SW2F,   (const char*)g_W2F + e*8192, 512, tid);
        stage16(bo + SW3F,   (const char*)g_W3F + e*4096, 256, tid);
        stage16(bo + SW1T33, (const char*)(g_W1T33 + e*64), 16, tid);
        stage16(bo + SB1, (const char*)(b1 + e*64), 16, tid);
        stage16(bo + SB2, (const char*)(b2 + e*64), 16, tid);
        stage16(bo + SB3, (const char*)(b3 + e*32),  8, tid);
    }
    stage16(sb + SGW1F, (const char*)g_GW1F, 512, tid);
    stage16(sb + SGW2F, (const char*)g_GW2F, 64, tid);
    stage16(sb + SGB1, (const char*)Gb1, 16, tid);
    stage16(sb + SGB2, (const char*)Gb2, 2, tid);
    asm volatile("cp.async.commit_group;" ::: "memory");

    float x[16], ksum[16], kk[16];
    #pragma unroll
    for (int c = 0; c < 16; c++) kk[c] = 0.f;
    #pragma unroll
    for (int j = 0; j < 4; j++){
        float2 a = *(const float2*)(x0 + row0*32 + j*8 + 2*q);
        float2 b = *(const float2*)(x0 + (row0+8)*32 + j*8 + 2*q);
        x[j*4+0] = a.x; x[j*4+1] = a.y; x[j*4+2] = b.x; x[j*4+3] = b.y;
        *(float2*)(out + row0*320 + j*8 + 2*q)     = a;
        *(float2*)(out + (row0+8)*320 + j*8 + 2*q) = b;
    }

    asm volatile("cp.async.wait_group 0;" ::: "memory");
    __syncthreads();    // the ONLY CTA-wide barrier

    #pragma unroll 1
    for (int s = 0; s < TPTS - 1; s++){
        const float t0 = tspan[s], t1 = tspan[s+1];
        const float dt = t1 - t0;
        #pragma unroll
        for (int c = 0; c < 16; c++) ksum[c] = 0.f;

        #pragma unroll 1
        for (int sub = 0; sub < 4; sub++){
            const float nc   = (sub == 0) ? 0.f : ((sub == 3) ? dt : 0.5f*dt);
            const float tcur = t0 + nc;

            // pack xin A-fragments (k = 0..31)
            u32 XA[8];
            #pragma unroll
            for (int jj = 0; jj < 2; jj++){
                int j0 = jj*2, j1 = jj*2+1;
                XA[jj*4+0] = f2h2(fmaf(nc, kk[j0*4+0], x[j0*4+0]), fmaf(nc, kk[j0*4+1], x[j0*4+1]));
                XA[jj*4+1] = f2h2(fmaf(nc, kk[j0*4+2], x[j0*4+2]), fmaf(nc, kk[j0*4+3], x[j0*4+3]));
                XA[jj*4+2] = f2h2(fmaf(nc, kk[j1*4+0], x[j1*4+0]), fmaf(nc, kk[j1*4+1], x[j1*4+1]));
                XA[jj*4+3] = f2h2(fmaf(nc, kk[j1*4+2], x[j1*4+2]), fmaf(nc, kk[j1*4+3], x[j1*4+3]));
            }

            float dxs[16];
            #pragma unroll
            for (int c = 0; c < 16; c++) dxs[c] = 0.f;

            u32 HA[16];
            u32 FR[64];   // F kept in registers: FR[e*8 + j2]

            #pragma unroll 1
            for (int e = 0; e < 8; e++){
                const char* wb = smem + e * EXPW;

                // ---- L1: N=64, K=32 MMA + scalar t-term
                float acc[32];
                #pragma unroll
                for (int j = 0; j < 8; j++){
                    uint2 bb = *(const uint2*)(wb + SW1F + j*256 + lane*8);
                    MMA4_INIT(&acc[j*4], XA[0],XA[1],XA[2],XA[3], bb);
                    bb = *(const uint2*)(wb + SW1F + (8+j)*256 + lane*8);
                    MMA4(&acc[j*4], XA[4],XA[5],XA[6],XA[7], bb);
                    float2 w33 = *(const float2*)(wb + SW1T33 + (j*8 + 2*q)*4);
                    float tw0 = tcur*w33.x, tw1 = tcur*w33.y;
                    acc[j*4+0] += tw0; acc[j*4+1] += tw1;
                    acc[j*4+2] += tw0; acc[j*4+3] += tw1;
                }
                EPI64(acc, wb + SB1, HA);

                // ---- L2: N=64, K=64
                #pragma unroll
                for (int j = 0; j < 8; j++){
                    uint2 bb = *(const uint2*)(wb + SW2F + (0*8+j)*256 + lane*8);
                    MMA4_INIT(&acc[j*4], HA[0],HA[1],HA[2],HA[3], bb);
                    #pragma unroll
                    for (int ks = 1; ks < 4; ks++){
                        bb = *(const uint2*)(wb + SW2F + (ks*8+j)*256 + lane*8);
                        MMA4(&acc[j*4], HA[ks*4+0],HA[ks*4+1],HA[ks*4+2],HA[ks*4+3], bb);
                    }
                }
                EPI64(acc, wb + SB2, HA);

                // ---- L3: N=32, K=64
                float a3[16];
                #pragma unroll
                for (int j = 0; j < 4; j++){
                    uint2 bb = *(const uint2*)(wb + SW3F + (0*4+j)*256 + lane*8);
                    MMA4_INIT(&a3[j*4], HA[0],HA[1],HA[2],HA[3], bb);
                    #pragma unroll
                    for (int ks = 1; ks < 4; ks++){
                        bb = *(const uint2*)(wb + SW3F + (ks*4+j)*256 + lane*8);
                        MMA4(&a3[j*4], HA[ks*4+0],HA[ks*4+1],HA[ks*4+2],HA[ks*4+3], bb);
                    }
                }
                {
                    const float* b3p = (const float*)(wb + SB3);
                    #pragma unroll
                    for (int j = 0; j < 4; j++){
                        float2 bv = *(const float2*)(b3p + j*8 + 2*q);
                        float c0 = a3[j*4+0] + bv.x, c1 = a3[j*4+1] + bv.y;
                        float c2 = a3[j*4+2] + bv.x, c3 = a3[j*4+3] + bv.y;
                        dxs[j*4+0] += c0; dxs[j*4+1] += c1; dxs[j*4+2] += c2; dxs[j*4+3] += c3;
                        FR[e*8 + j*2+0] = f2h2(c0, c1);
                        FR[e*8 + j*2+1] = f2h2(c2, c3);
                    }
                }
            } // experts

            // ---- gating GEMM1: A = [xin | dx_mean], N=64, K=64
            u32 DXF[8];
            #pragma unroll
            for (int jj = 0; jj < 2; jj++){
                int j0 = jj*2, j1 = jj*2+1;
                DXF[jj*4+0] = f2h2(dxs[j0*4+0]*0.125f, dxs[j0*4+1]*0.125f);
                DXF[jj*4+1] = f2h2(dxs[j0*4+2]*0.125f, dxs[j0*4+3]*0.125f);
                DXF[jj*4+2] = f2h2(dxs[j1*4+0]*0.125f, dxs[j1*4+1]*0.125f);
                DXF[jj*4+3] = f2h2(dxs[j1*4+2]*0.125f, dxs[j1*4+3]*0.125f);
            }
            {
                float acc[32];
                #pragma unroll
                for (int j = 0; j < 8; j++){
                    uint2 bb;
                    bb = *(const uint2*)(smem + SGW1F + (0*8+j)*256 + lane*8);
                    MMA4_INIT(&acc[j*4], XA[0],XA[1],XA[2],XA[3], bb);
                    bb = *(const uint2*)(smem + SGW1F + (1*8+j)*256 + lane*8);
                    MMA4(&acc[j*4], XA[4],XA[5],XA[6],XA[7], bb);
                    bb = *(const uint2*)(smem + SGW1F + (2*8+j)*256 + lane*8);
                    MMA4(&acc[j*4], DXF[0],DXF[1],DXF[2],DXF[3], bb);
                    bb = *(const uint2*)(smem + SGW1F + (3*8+j)*256 + lane*8);
                    MMA4(&acc[j*4], DXF[4],DXF[5],DXF[6],DXF[7], bb);
                }
                EPI64(acc, smem + SGB1, HA);
            }
            // ---- gating GEMM2: N=8 logits + softmax
            float w0, w1, w80, w81;
            {
                float z[4];
                uint2 bb = *(const uint2*)(smem + SGW2F + 0*256 + lane*8);
                MMA4_INIT(z, HA[0],HA[1],HA[2],HA[3], bb);
                #pragma unroll
                for (int ks = 1; ks < 4; ks++){
                    bb = *(const uint2*)(smem + SGW2F + ks*256 + lane*8);
                    MMA4(z, HA[ks*4+0],HA[ks*4+1],HA[ks*4+2],HA[ks*4+3], bb);
                }
                float2 bv = *(const float2*)((const float*)(smem + SGB2) + 2*q);
                z[0] += bv.x; z[1] += bv.y; z[2] += bv.x; z[3] += bv.y;
                float m0 = fmaxf(z[0], z[1]);
                m0 = fmaxf(m0, __shfl_xor_sync(0xffffffffu, m0, 1));
                m0 = fmaxf(m0, __shfl_xor_sync(0xffffffffu, m0, 2));
                float e0v = exp_fast(z[0]-m0), e1v = exp_fast(z[1]-m0);
                float s0 = e0v + e1v;
                s0 += __shfl_xor_sync(0xffffffffu, s0, 1);
                s0 += __shfl_xor_sync(0xffffffffu, s0, 2);
                float i0 = rcp_fast(s0);
                w0 = e0v*i0; w1 = e1v*i0;
                float m1 = fmaxf(z[2], z[3]);
                m1 = fmaxf(m1, __shfl_xor_sync(0xffffffffu, m1, 1));
                m1 = fmaxf(m1, __shfl_xor_sync(0xffffffffu, m1, 2));
                float e2v = exp_fast(z[2]-m1), e3v = exp_fast(z[3]-m1);
                float s1 = e2v + e3v;
                s1 += __shfl_xor_sync(0xffffffffu, s1, 1);
                s1 += __shfl_xor_sync(0xffffffffu, s1, 2);
                float i1 = rcp_fast(s1);
                w80 = e2v*i1; w81 = e3v*i1;
            }
            // exchange expert weights within quad (lane q holds experts 2q,2q+1)
            float wA[8], wB[8];
            #pragma unroll
            for (int qq = 0; qq < 4; qq++){
                int src = (lane & ~3) | qq;
                wA[2*qq+0] = __shfl_sync(0xffffffffu, w0,  src);
                wA[2*qq+1] = __shfl_sync(0xffffffffu, w1,  src);
                wB[2*qq+0] = __shfl_sync(0xffffffffu, w80, src);
                wB[2*qq+1] = __shfl_sync(0xffffffffu, w81, src);
            }
            // combine k = sum_e wgt[e] * f_e (F in registers)
            #pragma unroll
            for (int c = 0; c < 16; c++) kk[c] = 0.f;
            #pragma unroll
            for (int e2 = 0; e2 < 8; e2++){
                float va = wA[e2], vb = wB[e2];
                #pragma unroll
                for (int j = 0; j < 4; j++){
                    float2 t;
                    t = h22f2(FR[e2*8 + j*2+0]);
                    kk[j*4+0] = fmaf(va, t.x, kk[j*4+0]); kk[j*4+1] = fmaf(va, t.y, kk[j*4+1]);
                    t = h22f2(FR[e2*8 + j*2+1]);
                    kk[j*4+2] = fmaf(vb, t.x, kk[j*4+2]); kk[j*4+3] = fmaf(vb, t.y, kk[j*4+3]);
                }
            }
            const float ws = (sub == 0 || sub == 3) ? 1.f : 2.f;
            #pragma unroll
            for (int c = 0; c < 16; c++) ksum[c] = fmaf(ws, kk[c], ksum[c]);
        } // sub

        const float sc = dt * (1.f/6.f);
        #pragma unroll
        for (int c = 0; c < 16; c++) x[c] = fmaf(sc, ksum[c], x[c]);
        #pragma unroll
        for (int j = 0; j < 4; j++){
            *(float2*)(out + row0*320 + (s+1)*32 + j*8 + 2*q)     = make_float2(x[j*4+0], x[j*4+1]);
            *(float2*)(out + (row0+8)*320 + (s+1)*32 + j*8 + 2*q) = make_float2(x[j*4+2], x[j*4+3]);
        }
    } // step
}

extern "C" void kernel_launch(void* const* d_in, const int* in_sizes, int n_in,
                              void* d_out, int out_size)
{
    (void)in_sizes; (void)n_in; (void)out_size;
    conv_weights<<<128, 256>>>(
        (const float*)d_in[2],  (const float*)d_in[4], (const float*)d_in[6],
        (const float*)d_in[8],  (const float*)d_in[10]);
    cudaFuncSetAttribute(ameode_mma, cudaFuncAttributeMaxDynamicSharedMemorySize, SMEM_BYTES);
    ameode_mma<<<128, CTA, SMEM_BYTES>>>(
        (const float*)d_in[0],  (const float*)d_in[1],
        (const float*)d_in[3],  (const float*)d_in[5], (const float*)d_in[7],
        (const float*)d_in[9],  (const float*)d_in[11],
        (float*)d_out);
}